// round 1
// baseline (speedup 1.0000x reference)
#include <cuda_runtime.h>
#include <math.h>

#define D 128
#define MAX_NDST 50000
#define MAX_NSRC 100000
#define MAX_E    600000

// Scratch (static device globals -- no allocation allowed)
__device__ __align__(16) float g_a_dst[MAX_NDST * D];   // W1[:, :128] @ feat_dst + b1
__device__ __align__(16) float g_b_src[MAX_NSRC * D];   // W1[:, 128:] @ feat_src
__device__ __align__(16) float g_neigh[MAX_NDST * D];   // weighted aggregation
__device__ float g_ex[MAX_E];                            // exp(score) per edge
__device__ float g_denom[MAX_NDST];                      // per-dst softmax denominator

// ---------------------------------------------------------------------------
// init: zero neigh + denom
// ---------------------------------------------------------------------------
__global__ void init_kernel(int ndst) {
    int i = blockIdx.x * blockDim.x + threadIdx.x;
    int total = ndst * D;
    if (i < total) g_neigh[i] = 0.0f;
    if (i < ndst)  g_denom[i] = 0.0f;
}

// ---------------------------------------------------------------------------
// Tiled fp32 GEMM:  C[m, n] = act( sum_k A[m,k] * W[n, wbase + k] + bias[n] )
//   A is [M, 128] row-major; W is [128, ldw] row-major; C is [M, 128].
//   TWO=true: K=256, first 128 k's from A1 (W cols 0..127), next 128 from A2
//   (W cols 128..255).
// Block: 256 threads computes 64(M) x 128(N) tile. BK = 32.
// ---------------------------------------------------------------------------
template <bool TWO, bool RELU>
__global__ void __launch_bounds__(256) gemm_kernel(
    const float* __restrict__ A1,
    const float* __restrict__ A2,
    const float* __restrict__ W, int ldw, int wbase,
    const float* __restrict__ bias,
    float* __restrict__ C, int M)
{
    __shared__ float As[32][68];    // [k][m], padded
    __shared__ float Bs[32][132];   // [k][n], padded

    const int tid  = threadIdx.x;
    const int trow = tid >> 5;      // 0..7  -> rows trow*8 .. trow*8+7
    const int tcol = tid & 31;      // 0..31 -> cols tcol*4 .. tcol*4+3
    const int m0   = blockIdx.x * 64;

    float acc[8][4];
#pragma unroll
    for (int i = 0; i < 8; i++)
#pragma unroll
        for (int j = 0; j < 4; j++) acc[i][j] = 0.0f;

    const int nkt = TWO ? 8 : 4;
    for (int kt = 0; kt < nkt; kt++) {
        const int wcol = wbase + kt * 32;                 // W column offset
        const float* A = (TWO && kt >= 4) ? A2 : A1;
        const int ak0  = (TWO && kt >= 4) ? (kt - 4) * 32 : kt * 32;

        // --- load A tile (64 x 32) transposed into As[k][m] ---
#pragma unroll
        for (int t = 0; t < 2; t++) {
            int idx = tid + t * 256;          // 0..511 float4 slots
            int row = idx >> 3;               // 0..63
            int c4  = idx & 7;                // 0..7
            int m   = m0 + row;
            if (m >= M) m = M - 1;            // clamp (safe duplicate)
            float4 v = *(const float4*)(A + (size_t)m * D + ak0 + c4 * 4);
            As[c4 * 4 + 0][row] = v.x;
            As[c4 * 4 + 1][row] = v.y;
            As[c4 * 4 + 2][row] = v.z;
            As[c4 * 4 + 3][row] = v.w;
        }
        // --- load W tile (128 n x 32 k) into Bs[k][n] ---
#pragma unroll
        for (int t = 0; t < 4; t++) {
            int idx = tid + t * 256;          // 0..1023
            int n   = idx >> 3;               // 0..127
            int c4  = idx & 7;
            float4 v = *(const float4*)(W + (size_t)n * ldw + wcol + c4 * 4);
            Bs[c4 * 4 + 0][n] = v.x;
            Bs[c4 * 4 + 1][n] = v.y;
            Bs[c4 * 4 + 2][n] = v.z;
            Bs[c4 * 4 + 3][n] = v.w;
        }
        __syncthreads();

#pragma unroll
        for (int k = 0; k < 32; k++) {
            float4 a0 = *(const float4*)&As[k][trow * 8];
            float4 a1 = *(const float4*)&As[k][trow * 8 + 4];
            float4 b  = *(const float4*)&Bs[k][tcol * 4];
            float av[8] = {a0.x, a0.y, a0.z, a0.w, a1.x, a1.y, a1.z, a1.w};
            float bv[4] = {b.x, b.y, b.z, b.w};
#pragma unroll
            for (int i = 0; i < 8; i++)
#pragma unroll
                for (int j = 0; j < 4; j++)
                    acc[i][j] = fmaf(av[i], bv[j], acc[i][j]);
        }
        __syncthreads();
    }

    // --- epilogue ---
    const int n = tcol * 4;
    float4 bv = make_float4(0.f, 0.f, 0.f, 0.f);
    if (bias) bv = *(const float4*)(bias + n);
#pragma unroll
    for (int i = 0; i < 8; i++) {
        int m = m0 + trow * 8 + i;
        if (m < M) {
            float4 o;
            o.x = acc[i][0] + bv.x;
            o.y = acc[i][1] + bv.y;
            o.z = acc[i][2] + bv.z;
            o.w = acc[i][3] + bv.w;
            if (RELU) {
                o.x = fmaxf(o.x, 0.f); o.y = fmaxf(o.y, 0.f);
                o.z = fmaxf(o.z, 0.f); o.w = fmaxf(o.w, 0.f);
            }
            *(float4*)(C + (size_t)m * D + n) = o;
        }
    }
}

// ---------------------------------------------------------------------------
// Edge pass 1: score -> exp(score), denom accumulation.  One warp per edge.
// score = W2 . tanh(a_dst[dst] + b_src[src]) + b2.  (|score| <= sum|W2| ~ 28,
// so exp() cannot overflow -> no segment-max needed.)
// ---------------------------------------------------------------------------
__global__ void edge_score_kernel(const int* __restrict__ es,
                                  const int* __restrict__ ed,
                                  const float* __restrict__ W2,
                                  const float* __restrict__ b2,
                                  int E)
{
    int e    = (blockIdx.x * blockDim.x + threadIdx.x) >> 5;
    int lane = threadIdx.x & 31;
    if (e >= E) return;
    int s = es[e];
    int d = ed[e];

    float4 ad = ((const float4*)(g_a_dst + (size_t)d * D))[lane];
    float4 bs = ((const float4*)(g_b_src + (size_t)s * D))[lane];
    float4 w2 = ((const float4*)W2)[lane];

    float p = tanhf(ad.x + bs.x) * w2.x
            + tanhf(ad.y + bs.y) * w2.y
            + tanhf(ad.z + bs.z) * w2.z
            + tanhf(ad.w + bs.w) * w2.w;
#pragma unroll
    for (int o = 16; o; o >>= 1) p += __shfl_xor_sync(0xFFFFFFFFu, p, o);

    if (lane == 0) {
        float ex = expf(p + b2[0]);
        g_ex[e] = ex;
        atomicAdd(&g_denom[d], ex);
    }
}

// ---------------------------------------------------------------------------
// Edge pass 2: neigh[dst] += (ex/denom[dst]) * feat_src[src].  Warp per edge,
// vectorized global reduction (red.global.add.v4.f32, sm_90+).
// ---------------------------------------------------------------------------
__device__ __forceinline__ void red_add_v4(float* addr, float x, float y, float z, float w) {
    asm volatile("red.global.add.v4.f32 [%0], {%1,%2,%3,%4};"
                 :: "l"(addr), "f"(x), "f"(y), "f"(z), "f"(w)
                 : "memory");
}

__global__ void edge_aggregate_kernel(const int* __restrict__ es,
                                      const int* __restrict__ ed,
                                      const float* __restrict__ feat_src,
                                      int E)
{
    int e    = (blockIdx.x * blockDim.x + threadIdx.x) >> 5;
    int lane = threadIdx.x & 31;
    if (e >= E) return;
    int s = es[e];
    int d = ed[e];

    float w = g_ex[e] / g_denom[d];
    float4 m = ((const float4*)(feat_src + (size_t)s * D))[lane];
    red_add_v4(g_neigh + (size_t)d * D + lane * 4,
               w * m.x, w * m.y, w * m.z, w * m.w);
}

// ---------------------------------------------------------------------------
// Launcher
// ---------------------------------------------------------------------------
extern "C" void kernel_launch(void* const* d_in, const int* in_sizes, int n_in,
                              void* d_out, int out_size)
{
    const float* feat_src = (const float*)d_in[0];
    const float* feat_dst = (const float*)d_in[1];
    const float* W1       = (const float*)d_in[2];
    const float* b1       = (const float*)d_in[3];
    const float* W2       = (const float*)d_in[4];
    const float* b2       = (const float*)d_in[5];
    const float* Wfc      = (const float*)d_in[6];
    const float* bfc      = (const float*)d_in[7];
    const int*   es       = (const int*)d_in[8];
    const int*   ed       = (const int*)d_in[9];

    const int NSRC = in_sizes[0] / D;
    const int NDST = in_sizes[1] / D;
    const int E    = in_sizes[8];
    float* out = (float*)d_out;

    // Device addresses of scratch symbols (host-side &symbol is invalid)
    void *p_a, *p_b, *p_n;
    cudaGetSymbolAddress(&p_a, g_a_dst);
    cudaGetSymbolAddress(&p_b, g_b_src);
    cudaGetSymbolAddress(&p_n, g_neigh);
    float* a_dst = (float*)p_a;
    float* b_src = (float*)p_b;
    float* neigh = (float*)p_n;

    init_kernel<<<(NDST * D + 255) / 256, 256>>>(NDST);

    // a_dst = feat_dst @ W1[:, :128]^T + b1
    gemm_kernel<false, false><<<(NDST + 63) / 64, 256>>>(
        feat_dst, nullptr, W1, 2 * D, 0, b1, a_dst, NDST);

    // b_src = feat_src @ W1[:, 128:]^T
    gemm_kernel<false, false><<<(NSRC + 63) / 64, 256>>>(
        feat_src, nullptr, W1, 2 * D, D, nullptr, b_src, NSRC);

    // per-edge scores -> exp + denom
    edge_score_kernel<<<(E + 7) / 8, 256>>>(es, ed, W2, b2, E);

    // weighted aggregation into neigh
    edge_aggregate_kernel<<<(E + 7) / 8, 256>>>(es, ed, feat_src, E);

    // out = relu( feat_dst @ Wfc[:, :128]^T + neigh @ Wfc[:, 128:]^T + bfc )
    gemm_kernel<true, true><<<(NDST + 63) / 64, 256>>>(
        feat_dst, neigh, Wfc, 2 * D, 0, bfc, out, NDST);
}

// round 3
// speedup vs baseline: 1.2984x; 1.2984x over previous
#include <cuda_runtime.h>
#include <math.h>

#define D 128
#define MAX_NDST 50000
#define MAX_NSRC 100000
#define MAX_E    600000
#define SCAN_B   512

// Scratch (static device globals -- no allocation allowed)
__device__ __align__(16) float g_a_dst[MAX_NDST * D];   // feat_dst @ W1[:, :128]^T + b1
__device__ __align__(16) float g_b_src[MAX_NSRC * D];   // feat_src @ W1[:, 128:]^T
__device__ __align__(16) float g_neigh[MAX_NDST * D];   // softmax-weighted aggregation
__device__ int g_cnt[MAX_NDST];                          // per-dst degree
__device__ int g_off[MAX_NDST + 1];                      // CSR offsets
__device__ int g_cur[MAX_NDST];                          // scatter cursors
__device__ int g_srcs[MAX_E];                            // CSR: src id per slot
__device__ int g_part[256];                              // scan partials

// ---------------------------------------------------------------------------
// fast tanh (MUFU.TANH, sm_75+)
// ---------------------------------------------------------------------------
__device__ __forceinline__ float tanha(float x) {
    float y;
    asm("tanh.approx.f32 %0, %1;" : "=f"(y) : "f"(x));
    return y;
}

// ---------------------------------------------------------------------------
// CSR build: zero counts -> count -> scan(3) -> scatter
// ---------------------------------------------------------------------------
__global__ void zero_cnt_kernel(int n) {
    int i = blockIdx.x * blockDim.x + threadIdx.x;
    if (i < n) g_cnt[i] = 0;
}

__global__ void count_kernel(const int* __restrict__ ed, int E) {
    int e = blockIdx.x * blockDim.x + threadIdx.x;
    if (e < E) atomicAdd(&g_cnt[ed[e]], 1);
}

__device__ __forceinline__ int warp_incl_scan(int v, int lane) {
#pragma unroll
    for (int o = 1; o < 32; o <<= 1) {
        int t = __shfl_up_sync(0xFFFFFFFFu, v, o);
        if (lane >= o) v += t;
    }
    return v;
}

// per-block sums of g_cnt
__global__ void __launch_bounds__(SCAN_B) scan1_kernel(int n) {
    __shared__ int wsum[SCAN_B / 32];
    int tid  = threadIdx.x;
    int lane = tid & 31;
    int wid  = tid >> 5;
    int i = blockIdx.x * SCAN_B + tid;
    int v = (i < n) ? g_cnt[i] : 0;
#pragma unroll
    for (int o = 16; o; o >>= 1) v += __shfl_xor_sync(0xFFFFFFFFu, v, o);
    if (lane == 0) wsum[wid] = v;
    __syncthreads();
    if (wid == 0) {
        int s = (lane < SCAN_B / 32) ? wsum[lane] : 0;
#pragma unroll
        for (int o = 16; o; o >>= 1) s += __shfl_xor_sync(0xFFFFFFFFu, s, o);
        if (lane == 0) g_part[blockIdx.x] = s;
    }
}

// exclusive scan of partials (single block, nb <= 128) + write g_off[n] = E
__global__ void scan2_kernel(int nb, int n, int E) {
    __shared__ int sh[128];
    int tid = threadIdx.x;
    int v = (tid < nb) ? g_part[tid] : 0;
    sh[tid] = v;
    __syncthreads();
#pragma unroll
    for (int o = 1; o < 128; o <<= 1) {
        int t = (tid >= o) ? sh[tid - o] : 0;
        __syncthreads();
        sh[tid] += t;
        __syncthreads();
    }
    if (tid < nb) g_part[tid] = sh[tid] - v;   // exclusive
    if (tid == 0) g_off[n] = E;
}

// block-local exclusive scan + partial offset -> g_off, g_cur
__global__ void __launch_bounds__(SCAN_B) scan3_kernel(int n) {
    __shared__ int wsum[SCAN_B / 32];
    int tid  = threadIdx.x;
    int lane = tid & 31;
    int wid  = tid >> 5;
    int i = blockIdx.x * SCAN_B + tid;
    int v = (i < n) ? g_cnt[i] : 0;
    int incl = warp_incl_scan(v, lane);
    if (lane == 31) wsum[wid] = incl;
    __syncthreads();
    if (wid == 0) {
        int s = (lane < SCAN_B / 32) ? wsum[lane] : 0;
        int si = warp_incl_scan(s, lane);
        if (lane < SCAN_B / 32) wsum[lane] = si - s;  // exclusive warp offsets
    }
    __syncthreads();
    int excl = incl - v + wsum[wid] + g_part[blockIdx.x];
    if (i < n) {
        g_off[i] = excl;
        g_cur[i] = excl;
    }
}

__global__ void scatter_kernel(const int* __restrict__ es,
                               const int* __restrict__ ed, int E) {
    int e = blockIdx.x * blockDim.x + threadIdx.x;
    if (e < E) {
        int pos = atomicAdd(&g_cur[ed[e]], 1);
        g_srcs[pos] = es[e];
    }
}

// ---------------------------------------------------------------------------
// Tiled fp32 GEMM (at SIMT FFMA ceiling):
//   C[m, n] = act( sum_k A[m,k] * W[n, wbase + k] + bias[n] )
//   TWO=true: K=256 split across A1 (W cols 0..127) and A2 (W cols 128..255).
// Block: 256 threads computes 64(M) x 128(N) tile. BK = 32.
// ---------------------------------------------------------------------------
template <bool TWO, bool RELU>
__global__ void __launch_bounds__(256) gemm_kernel(
    const float* __restrict__ A1,
    const float* __restrict__ A2,
    const float* __restrict__ W, int ldw, int wbase,
    const float* __restrict__ bias,
    float* __restrict__ C, int M)
{
    __shared__ float As[32][68];
    __shared__ float Bs[32][132];

    const int tid  = threadIdx.x;
    const int trow = tid >> 5;
    const int tcol = tid & 31;
    const int m0   = blockIdx.x * 64;

    float acc[8][4];
#pragma unroll
    for (int i = 0; i < 8; i++)
#pragma unroll
        for (int j = 0; j < 4; j++) acc[i][j] = 0.0f;

    const int nkt = TWO ? 8 : 4;
    for (int kt = 0; kt < nkt; kt++) {
        const int wcol = wbase + kt * 32;
        const float* A = (TWO && kt >= 4) ? A2 : A1;
        const int ak0  = (TWO && kt >= 4) ? (kt - 4) * 32 : kt * 32;

#pragma unroll
        for (int t = 0; t < 2; t++) {
            int idx = tid + t * 256;
            int row = idx >> 3;
            int c4  = idx & 7;
            int m   = m0 + row;
            if (m >= M) m = M - 1;
            float4 v = *(const float4*)(A + (size_t)m * D + ak0 + c4 * 4);
            As[c4 * 4 + 0][row] = v.x;
            As[c4 * 4 + 1][row] = v.y;
            As[c4 * 4 + 2][row] = v.z;
            As[c4 * 4 + 3][row] = v.w;
        }
#pragma unroll
        for (int t = 0; t < 4; t++) {
            int idx = tid + t * 256;
            int n   = idx >> 3;
            int c4  = idx & 7;
            float4 v = *(const float4*)(W + (size_t)n * ldw + wcol + c4 * 4);
            Bs[c4 * 4 + 0][n] = v.x;
            Bs[c4 * 4 + 1][n] = v.y;
            Bs[c4 * 4 + 2][n] = v.z;
            Bs[c4 * 4 + 3][n] = v.w;
        }
        __syncthreads();

#pragma unroll
        for (int k = 0; k < 32; k++) {
            float4 a0 = *(const float4*)&As[k][trow * 8];
            float4 a1 = *(const float4*)&As[k][trow * 8 + 4];
            float4 b  = *(const float4*)&Bs[k][tcol * 4];
            float av[8] = {a0.x, a0.y, a0.z, a0.w, a1.x, a1.y, a1.z, a1.w};
            float bv[4] = {b.x, b.y, b.z, b.w};
#pragma unroll
            for (int i = 0; i < 8; i++)
#pragma unroll
                for (int j = 0; j < 4; j++)
                    acc[i][j] = fmaf(av[i], bv[j], acc[i][j]);
        }
        __syncthreads();
    }

    const int n = tcol * 4;
    float4 bv = make_float4(0.f, 0.f, 0.f, 0.f);
    if (bias) bv = *(const float4*)(bias + n);
#pragma unroll
    for (int i = 0; i < 8; i++) {
        int m = m0 + trow * 8 + i;
        if (m < M) {
            float4 o;
            o.x = acc[i][0] + bv.x;
            o.y = acc[i][1] + bv.y;
            o.z = acc[i][2] + bv.z;
            o.w = acc[i][3] + bv.w;
            if (RELU) {
                o.x = fmaxf(o.x, 0.f); o.y = fmaxf(o.y, 0.f);
                o.z = fmaxf(o.z, 0.f); o.w = fmaxf(o.w, 0.f);
            }
            *(float4*)(C + (size_t)m * D + n) = o;
        }
    }
}

// ---------------------------------------------------------------------------
// Fused attention: one warp per dst node, single pass over its CSR edges.
//   score_e = W2 . tanh(a_dst[d] + b_src[s_e]) + b2   (no segment-max needed:
//             |score| <= sum|W2| ~ 28, exp cannot overflow)
//   neigh[d] = (sum_e exp(score_e) * feat_src[s_e]) / (sum_e exp(score_e))
// Next-index software pipelining hides the idx->row dependent-load chain.
// ---------------------------------------------------------------------------
__global__ void __launch_bounds__(256) fused_attn_kernel(
    const float* __restrict__ feat_src,
    const float* __restrict__ W2,
    const float* __restrict__ b2,
    int ndst)
{
    int w    = (blockIdx.x * blockDim.x + threadIdx.x) >> 5;
    int lane = threadIdx.x & 31;
    if (w >= ndst) return;

    int beg = g_off[w];
    int end = g_off[w + 1];
    float4* nrow = (float4*)(g_neigh + (size_t)w * D);

    if (beg == end) {                 // 0-degree: neigh = 0 (matches ref)
        nrow[lane] = make_float4(0.f, 0.f, 0.f, 0.f);
        return;
    }

    float4 ad = ((const float4*)(g_a_dst + (size_t)w * D))[lane];
    float4 w2 = ((const float4*)W2)[lane];
    float b2v = b2[0];

    float denom = 0.0f;
    float4 acc = make_float4(0.f, 0.f, 0.f, 0.f);

    int s = __ldg(&g_srcs[beg]);
    for (int i = beg; i < end; i++) {
        int s_next = (i + 1 < end) ? __ldg(&g_srcs[i + 1]) : 0;
        float4 bs = ((const float4*)(g_b_src + (size_t)s * D))[lane];
        float4 m  = ((const float4*)(feat_src + (size_t)s * D))[lane];

        float p = tanha(ad.x + bs.x) * w2.x
                + tanha(ad.y + bs.y) * w2.y
                + tanha(ad.z + bs.z) * w2.z
                + tanha(ad.w + bs.w) * w2.w;
#pragma unroll
        for (int o = 16; o; o >>= 1) p += __shfl_xor_sync(0xFFFFFFFFu, p, o);

        float ex = __expf(p + b2v);
        denom += ex;
        acc.x = fmaf(ex, m.x, acc.x);
        acc.y = fmaf(ex, m.y, acc.y);
        acc.z = fmaf(ex, m.z, acc.z);
        acc.w = fmaf(ex, m.w, acc.w);
        s = s_next;
    }

    float inv = 1.0f / denom;
    acc.x *= inv; acc.y *= inv; acc.z *= inv; acc.w *= inv;
    nrow[lane] = acc;
}

// ---------------------------------------------------------------------------
// Launcher
// ---------------------------------------------------------------------------
extern "C" void kernel_launch(void* const* d_in, const int* in_sizes, int n_in,
                              void* d_out, int out_size)
{
    const float* feat_src = (const float*)d_in[0];
    const float* feat_dst = (const float*)d_in[1];
    const float* W1       = (const float*)d_in[2];
    const float* b1       = (const float*)d_in[3];
    const float* W2       = (const float*)d_in[4];
    const float* b2       = (const float*)d_in[5];
    const float* Wfc      = (const float*)d_in[6];
    const float* bfc      = (const float*)d_in[7];
    const int*   es       = (const int*)d_in[8];
    const int*   ed       = (const int*)d_in[9];

    const int NSRC = in_sizes[0] / D;
    const int NDST = in_sizes[1] / D;
    const int E    = in_sizes[8];
    float* out = (float*)d_out;

    void *p_a, *p_b, *p_n;
    cudaGetSymbolAddress(&p_a, g_a_dst);
    cudaGetSymbolAddress(&p_b, g_b_src);
    cudaGetSymbolAddress(&p_n, g_neigh);
    float* a_dst = (float*)p_a;
    float* b_src = (float*)p_b;
    float* neigh = (float*)p_n;

    // --- CSR build ---
    zero_cnt_kernel<<<(NDST + 255) / 256, 256>>>(NDST);
    count_kernel<<<(E + 255) / 256, 256>>>(ed, E);
    int nb = (NDST + SCAN_B - 1) / SCAN_B;     // <= 128
    scan1_kernel<<<nb, SCAN_B>>>(NDST);
    scan2_kernel<<<1, 128>>>(nb, NDST, E);
    scan3_kernel<<<nb, SCAN_B>>>(NDST);
    scatter_kernel<<<(E + 255) / 256, 256>>>(es, ed, E);

    // --- node GEMMs ---
    gemm_kernel<false, false><<<(NDST + 63) / 64, 256>>>(
        feat_dst, nullptr, W1, 2 * D, 0, b1, a_dst, NDST);
    gemm_kernel<false, false><<<(NSRC + 63) / 64, 256>>>(
        feat_src, nullptr, W1, 2 * D, D, nullptr, b_src, NSRC);

    // --- fused edge softmax + aggregation (single pass) ---
    fused_attn_kernel<<<(NDST * 32 + 255) / 256, 256>>>(feat_src, W2, b2, NDST);

    // --- out = relu( [feat_dst, neigh] @ Wfc^T + bfc ) ---
    gemm_kernel<true, true><<<(NDST + 63) / 64, 256>>>(
        feat_dst, neigh, Wfc, 2 * D, 0, bfc, out, NDST);
}